// round 17
// baseline (speedup 1.0000x reference)
#include <cuda_runtime.h>
#include <cuda_bf16.h>
#include <mma.h>
#include <math.h>
#include <stdint.h>

using namespace nvcuda;
typedef __nv_bfloat16 bf16;

// ---------------- Problem constants ----------------
#define PATCHES 64
#define DIMD    512
#define HEADS   8
#define DH      64
#define DFF     1024
#define KP      128
#define T1      257
#define B1      64
#define T2      65
#define B2      256
#define NTOK1   (B1*T1)      // 16448
#define NTOK1P  16512        // 129*128
#define NTOK2   (B2*T2)      // 16640
#define LDQKV   (3*DIMD)     // 1536

// ---------------- Scratch (device globals) --------
__device__ float g_xt[NTOK1P*DIMD];
__device__ bf16  b_xt[NTOK1P*DIMD];
__device__ bf16  b_qkv[(NTOK2+128)*LDQKV];   // oversized; tail rows never written -> zeros
__device__ bf16  b_att[NTOK2*DIMD];
__device__ float g_y1[NTOK1P*DIMD];
__device__ float g_ys[NTOK2*DIMD];
__device__ bf16  b_ys[NTOK2*DIMD];
__device__ bf16  b_kvp[B2*HEADS*2*KP*DH];
__device__ bf16  b_ffh[NTOK2*DFF];
__device__ bf16  b_out[NTOK2*DIMD];
// bf16 weights
__device__ bf16 w_qkv_t[DIMD*LDQKV];
__device__ bf16 w_o_t[DIMD*DIMD];
__device__ bf16 w_qkv_s[DIMD*LDQKV];
__device__ bf16 w_o_s[DIMD*DIMD];
__device__ bf16 w_1[DIMD*DFF];
__device__ bf16 w_2[DFF*DIMD];
__device__ bf16 w_ETp[128*96];               // E^T padded: [kk][j], j>=65 zero

__device__ __forceinline__ float gelu_exact(float v) {
    return 0.5f * v * (1.0f + erff(v * 0.70710678118654752f));
}

// ---------------- cp.async helpers ----------------
__device__ __forceinline__ void cp16(void* dst, const void* src) {
    uint32_t d = (uint32_t)__cvta_generic_to_shared(dst);
    asm volatile("cp.async.cg.shared.global [%0], [%1], 16;\n" :: "r"(d), "l"(src));
}
__device__ __forceinline__ void cp_commit() {
    asm volatile("cp.async.commit_group;\n");
}
template <int NW>
__device__ __forceinline__ void cp_wait() {
    asm volatile("cp.async.wait_group %0;\n" :: "n"(NW));
}

// ---------------- multi-segment fp32 -> bf16 convert ----------------
struct ConvSegs {
    const float* src[6];
    bf16* dst[6];
    int n4[6];
};
__global__ void f2b_multi(ConvSegs s) {
    int seg = blockIdx.y;
    int i = blockIdx.x * 256 + threadIdx.x;
    if (i >= s.n4[seg]) return;
    float4 v = ((const float4*)s.src[seg])[i];
    __nv_bfloat162* d = (__nv_bfloat162*)(s.dst[seg] + (size_t)i * 4);
    d[0] = __nv_bfloat162{__float2bfloat16(v.x), __float2bfloat16(v.y)};
    d[1] = __nv_bfloat162{__float2bfloat16(v.z), __float2bfloat16(v.w)};
}

// E^T padded build: ET[kk*96 + j] = E[j*KP + kk] (j<65) else 0
__global__ void build_ET(const float* __restrict__ E, bf16* __restrict__ ET) {
    int idx = blockIdx.x * 256 + threadIdx.x;
    if (idx >= 128 * 96) return;
    int kk = idx / 96, j = idx % 96;
    ET[idx] = __float2bfloat16(j < T2 ? E[(size_t)j * KP + kk] : 0.f);
}

// ---------------- Rearrange kernels ----------------
__global__ void build_xt_kernel(const float* __restrict__ x, float* __restrict__ xt,
                                bf16* __restrict__ xtb) {
    int token = blockIdx.x;
    size_t doff = (size_t)token * DIMD + threadIdx.x * 4;
    int s = token / T1, t = token % T1;
    float4 v;
    if (s >= B1) v = make_float4(0.f, 0.f, 0.f, 0.f);
    else {
        size_t src_tok = (t == 0) ? 0 : (size_t)(1 + (size_t)(t - 1) * PATCHES + s);
        v = *(const float4*)(x + src_tok * DIMD + threadIdx.x * 4);
    }
    *(float4*)(xt + doff) = v;
    __nv_bfloat162* d = (__nv_bfloat162*)(xtb + doff);
    d[0] = __nv_bfloat162{__float2bfloat16(v.x), __float2bfloat16(v.y)};
    d[1] = __nv_bfloat162{__float2bfloat16(v.z), __float2bfloat16(v.w)};
}

__global__ void build_ys_kernel(const float* __restrict__ y1, float* __restrict__ ys,
                                bf16* __restrict__ ysb) {
    int token = blockIdx.x;
    int i = token / T2, j = token % T2;
    size_t src_tok = (j == 0) ? (size_t)(i % 64) * T1
                              : (size_t)(j - 1) * T1 + 1 + i;
    float4 v = *(const float4*)(y1 + src_tok * DIMD + threadIdx.x * 4);
    size_t doff = (size_t)token * DIMD + threadIdx.x * 4;
    *(float4*)(ys + doff) = v;
    __nv_bfloat162* d = (__nv_bfloat162*)(ysb + doff);
    d[0] = __nv_bfloat162{__float2bfloat16(v.x), __float2bfloat16(v.y)};
    d[1] = __nv_bfloat162{__float2bfloat16(v.z), __float2bfloat16(v.w)};
}

// ================= bf16 dense GEMM: 128x128, BK=32, cp.async 2-stage =========
#define EPI_R    1
#define EPI_BIAS 2
#define EPI_GELU 4
#define EPI_F32  8
#define EPI_B16  16

#define ALDb 40
#define BLDb 136
#define PLD  20

__global__ void __launch_bounds__(256, 2)
gemm_bf128(const bf16* __restrict__ A, const bf16* __restrict__ B,
           float* __restrict__ Cf, bf16* __restrict__ Cb,
           const float* __restrict__ bias, const float* __restrict__ R,
           int N, int K, int epi)
{
    __shared__ __align__(16) bf16 sA[2][128 * ALDb];
    __shared__ __align__(16) bf16 sB[2][32 * BLDb];

    int tid = threadIdx.x;
    int warp = tid >> 5, lane = tid & 31;
    int wm = warp >> 2, wn = warp & 3;
    int row0 = blockIdx.y * 128;
    int col0 = blockIdx.x * 128;

    const bf16* Aptr = A + (size_t)row0 * K;
    const bf16* Bptr = B + col0;

    wmma::fragment<wmma::accumulator, 16, 16, 16, float> acc[4][2];
#pragma unroll
    for (int i = 0; i < 4; i++)
#pragma unroll
        for (int j = 0; j < 2; j++) wmma::fill_fragment(acc[i][j], 0.f);

    const int a_r0 = (tid      ) >> 2, a_c0 = (tid      ) & 3;
    const int a_r1 = (tid + 256) >> 2, a_c1 = (tid + 256) & 3;
    const int b_r0 = (tid      ) >> 4, b_c0 = (tid      ) & 15;
    const int b_r1 = (tid + 256) >> 4, b_c1 = (tid + 256) & 15;

    const int nch = K >> 5;

    cp16(&sA[0][a_r0 * ALDb + a_c0 * 8], Aptr + (size_t)a_r0 * K + a_c0 * 8);
    cp16(&sA[0][a_r1 * ALDb + a_c1 * 8], Aptr + (size_t)a_r1 * K + a_c1 * 8);
    cp16(&sB[0][b_r0 * BLDb + b_c0 * 8], Bptr + (size_t)b_r0 * N + b_c0 * 8);
    cp16(&sB[0][b_r1 * BLDb + b_c1 * 8], Bptr + (size_t)b_r1 * N + b_c1 * 8);
    cp_commit();

    for (int it = 0; it < nch; it++) {
        int buf = it & 1;
        if (it + 1 < nch) {
            int k0 = (it + 1) * 32;
            int nb = buf ^ 1;
            cp16(&sA[nb][a_r0 * ALDb + a_c0 * 8], Aptr + (size_t)a_r0 * K + k0 + a_c0 * 8);
            cp16(&sA[nb][a_r1 * ALDb + a_c1 * 8], Aptr + (size_t)a_r1 * K + k0 + a_c1 * 8);
            cp16(&sB[nb][b_r0 * BLDb + b_c0 * 8], Bptr + (size_t)(k0 + b_r0) * N + b_c0 * 8);
            cp16(&sB[nb][b_r1 * BLDb + b_c1 * 8], Bptr + (size_t)(k0 + b_r1) * N + b_c1 * 8);
            cp_commit();
            cp_wait<1>();
        } else {
            cp_wait<0>();
        }
        __syncthreads();

#pragma unroll
        for (int ks = 0; ks < 2; ks++) {
            wmma::fragment<wmma::matrix_a, 16, 16, 16, bf16, wmma::row_major> af[4];
            wmma::fragment<wmma::matrix_b, 16, 16, 16, bf16, wmma::row_major> bf_[2];
#pragma unroll
            for (int i = 0; i < 4; i++)
                wmma::load_matrix_sync(af[i], &sA[buf][(wm * 64 + i * 16) * ALDb + ks * 16], ALDb);
#pragma unroll
            for (int j = 0; j < 2; j++)
                wmma::load_matrix_sync(bf_[j], &sB[buf][(ks * 16) * BLDb + wn * 32 + j * 16], BLDb);
#pragma unroll
            for (int i = 0; i < 4; i++)
#pragma unroll
                for (int j = 0; j < 2; j++)
                    wmma::mma_sync(acc[i][j], af[i], bf_[j], acc[i][j]);
        }
        __syncthreads();
    }

    float* patch = reinterpret_cast<float*>(&sA[0][0]) + warp * 16 * PLD;
    int pr = lane >> 1;
    int pc = (lane & 1) * 8;
#pragma unroll
    for (int i = 0; i < 4; i++) {
#pragma unroll
        for (int j = 0; j < 2; j++) {
            wmma::store_matrix_sync(patch, acc[i][j], PLD, wmma::mem_row_major);
            __syncwarp();
            int grow = row0 + wm * 64 + i * 16 + pr;
            int gcol = col0 + wn * 32 + j * 16 + pc;
#pragma unroll
            for (int h = 0; h < 2; h++) {
                float4 v = *(float4*)&patch[pr * PLD + pc + h * 4];
                size_t off = (size_t)grow * N + gcol + h * 4;
                if (epi & EPI_BIAS) {
                    float4 bb = *(const float4*)&bias[gcol + h * 4];
                    v.x += bb.x; v.y += bb.y; v.z += bb.z; v.w += bb.w;
                }
                if (epi & EPI_GELU) {
                    v.x = gelu_exact(v.x); v.y = gelu_exact(v.y);
                    v.z = gelu_exact(v.z); v.w = gelu_exact(v.w);
                }
                if (epi & EPI_R) {
                    float4 rr = *(const float4*)&R[off];
                    v.x += rr.x; v.y += rr.y; v.z += rr.z; v.w += rr.w;
                }
                if (epi & EPI_F32) *(float4*)&Cf[off] = v;
                if (epi & EPI_B16) {
                    __nv_bfloat162* d = (__nv_bfloat162*)(Cb + off);
                    d[0] = __nv_bfloat162{__float2bfloat16(v.x), __float2bfloat16(v.y)};
                    d[1] = __nv_bfloat162{__float2bfloat16(v.z), __float2bfloat16(v.w)};
                }
            }
            __syncwarp();
        }
    }
}

// ================= Fused attention: QK^T -> softmax -> P@V, one launch =======
// Per block: 64 Q rows (blockIdx.x tile), one (batch, head) = blockIdx.y.
// NKT: # of 64-key tiles; LK: real key count; PC: padded P cols (mult of 32);
// SLD: fp32 score row ld (>= NKT*64 + pad); PLDD: bf16 P row ld.
// Dynamic smem: sQ[64*72] bf16 | sK[64*72] bf16 | sS[64*SLD] f32 | sP[64*PLDD] bf16
template<int NKT, int LK, int PC, int SLD, int PLDD>
__global__ void __launch_bounds__(256)
fused_attn(const bf16* __restrict__ qp, long qz0, int ldq,
           const bf16* __restrict__ kp, long kz0, long kz1, int ldk,
           const bf16* __restrict__ vp, long vz0, long vz1, int ldv,
           bf16* __restrict__ op, long oz0, int Mvalid, float scale)
{
    extern __shared__ __align__(16) char smem[];
    bf16*  sQ = (bf16*)smem;
    bf16*  sK = (bf16*)(smem + 64 * 72 * 2);
    float* sS = (float*)(smem + 2 * 64 * 72 * 2);
    bf16*  sP = (bf16*)(smem + 2 * 64 * 72 * 2 + 64 * SLD * 4);

    int z = blockIdx.y, zo = z >> 3, zi = z & 7;
    const bf16* Q = qp + (size_t)zo * qz0 + (size_t)zi * 64;
    const bf16* K = kp + (size_t)zo * kz0 + (size_t)zi * kz1;
    const bf16* V = vp + (size_t)zo * vz0 + (size_t)zi * vz1;
    int row0 = blockIdx.x * 64;
    int tid = threadIdx.x, warp = tid >> 5, lane = tid & 31;
    int wm = warp >> 1, wn = warp & 1;

    // Q tile 64x64 (guard-free: buffers oversized / tails zero)
#pragma unroll
    for (int l = 0; l < 2; l++) {
        int idx = tid + l * 256, r = idx >> 3, c8 = idx & 7;
        *(float4*)&sQ[r * 72 + c8 * 8] = *(const float4*)(Q + (size_t)(row0 + r) * ldq + c8 * 8);
    }

    // ---- QK^T into fp32 smem ----
    for (int kt = 0; kt < NKT; kt++) {
        __syncthreads();
#pragma unroll
        for (int l = 0; l < 2; l++) {
            int idx = tid + l * 256, r = idx >> 3, c8 = idx & 7;
            *(float4*)&sK[r * 72 + c8 * 8] = *(const float4*)(K + (size_t)(kt * 64 + r) * ldk + c8 * 8);
        }
        __syncthreads();
        wmma::fragment<wmma::accumulator, 16, 16, 16, float> c0, c1;
        wmma::fill_fragment(c0, 0.f);
        wmma::fill_fragment(c1, 0.f);
#pragma unroll
        for (int kk = 0; kk < 64; kk += 16) {
            wmma::fragment<wmma::matrix_a, 16, 16, 16, bf16, wmma::row_major> a;
            wmma::fragment<wmma::matrix_b, 16, 16, 16, bf16, wmma::col_major> b0, b1;
            wmma::load_matrix_sync(a, &sQ[(wm * 16) * 72 + kk], 72);
            wmma::load_matrix_sync(b0, &sK[(wn * 32) * 72 + kk], 72);
            wmma::load_matrix_sync(b1, &sK[(wn * 32 + 16) * 72 + kk], 72);
            wmma::mma_sync(c0, a, b0, c0);
            wmma::mma_sync(c1, a, b1, c1);
        }
        wmma::store_matrix_sync(&sS[(wm * 16) * SLD + kt * 64 + wn * 32], c0, SLD, wmma::mem_row_major);
        wmma::store_matrix_sync(&sS[(wm * 16) * SLD + kt * 64 + wn * 32 + 16], c1, SLD, wmma::mem_row_major);
    }
    __syncthreads();

    // ---- softmax over LK real keys, write bf16 P (zero pad to PC) ----
#pragma unroll
    for (int rr = 0; rr < 8; rr++) {
        int r = warp * 8 + rr;
        float* srow = &sS[r * SLD];
        float mx = -1e30f;
        for (int i = lane; i < LK; i += 32) mx = fmaxf(mx, srow[i]);
#pragma unroll
        for (int s = 16; s; s >>= 1) mx = fmaxf(mx, __shfl_xor_sync(0xffffffffu, mx, s));
        float sum = 0.f;
        for (int i = lane; i < LK; i += 32) sum += __expf((srow[i] - mx) * scale);
#pragma unroll
        for (int s = 16; s; s >>= 1) sum += __shfl_xor_sync(0xffffffffu, sum, s);
        float inv = 1.f / sum;
        bf16* prow = &sP[r * PLDD];
        for (int i = lane; i < LK; i += 32)
            prow[i] = __float2bfloat16(__expf((srow[i] - mx) * scale) * inv);
        for (int i = LK + lane; i < PC; i += 32)
            prow[i] = __float2bfloat16(0.f);
    }

    // ---- P @ V ----
    wmma::fragment<wmma::accumulator, 16, 16, 16, float> o0, o1;
    wmma::fill_fragment(o0, 0.f);
    wmma::fill_fragment(o1, 0.f);
    for (int ch = 0; ch < PC / 32; ch++) {
        __syncthreads();
        {
            int r = tid >> 3, c8 = tid & 7;
            *(float4*)&sK[r * 72 + c8 * 8] = *(const float4*)(V + (size_t)(ch * 32 + r) * ldv + c8 * 8);
        }
        __syncthreads();
#pragma unroll
        for (int ks = 0; ks < 2; ks++) {
            wmma::fragment<wmma::matrix_a, 16, 16, 16, bf16, wmma::row_major> a;
            wmma::fragment<wmma::matrix_b, 16, 16, 16, bf16, wmma::row_major> b0, b1;
            wmma::load_matrix_sync(a, &sP[(wm * 16) * PLDD + ch * 32 + ks * 16], PLDD);
            wmma::load_matrix_sync(b0, &sK[(ks * 16) * 72 + wn * 32], 72);
            wmma::load_matrix_sync(b1, &sK[(ks * 16) * 72 + wn * 32 + 16], 72);
            wmma::mma_sync(o0, a, b0, o0);
            wmma::mma_sync(o1, a, b1, o1);
        }
    }
    __syncthreads();
    wmma::store_matrix_sync(&sS[(wm * 16) * 68 + wn * 32], o0, 68, wmma::mem_row_major);
    wmma::store_matrix_sync(&sS[(wm * 16) * 68 + wn * 32 + 16], o1, 68, wmma::mem_row_major);
    __syncthreads();

    bf16* O = op + (size_t)zo * oz0 + (size_t)zi * 64;
    for (int idx = tid; idx < 64 * 64; idx += 256) {
        int r = idx >> 6, c = idx & 63;
        if (row0 + r < Mvalid)
            O[(size_t)(row0 + r) * DIMD + c] = __float2bfloat16(sS[r * 68 + c]);
    }
}

// ================= Linformer projection on tensor cores =====================
// kvp(kk, n) = sum_j ET[kk][j] * qkv[i*65 + j][512 + n],  K padded to 96.
// grid: (8 n-tiles of 128, 256 frames)
__global__ void __launch_bounds__(256)
eproj_tc(const bf16* __restrict__ ET, const bf16* __restrict__ qkv,
         bf16* __restrict__ kvp)
{
    __shared__ __align__(16) bf16 sA[128 * 104];
    __shared__ __align__(16) bf16 sB[96 * 136];

    int i = blockIdx.y, nt = blockIdx.x;
    int tid = threadIdx.x, warp = tid >> 5, lane = tid & 31;
    const bf16* Bp = qkv + (size_t)i * T2 * LDQKV + 512 + nt * 128;

#pragma unroll
    for (int l = 0; l < 6; l++) {
        int idx = tid + l * 256;
        int r = idx / 12, c8 = idx % 12;
        *(float4*)&sA[r * 104 + c8 * 8] = *(const float4*)(ET + r * 96 + c8 * 8);
    }
#pragma unroll
    for (int l = 0; l < 6; l++) {
        int idx = tid + l * 256;
        int r = idx >> 4, c8 = idx & 15;
        *(float4*)&sB[r * 136 + c8 * 8] = *(const float4*)(Bp + (size_t)r * LDQKV + c8 * 8);
    }
    __syncthreads();

    int wm = warp >> 1, wn = warp & 1;     // warp tile 32x64
    wmma::fragment<wmma::accumulator, 16, 16, 16, float> acc[2][4];
#pragma unroll
    for (int a = 0; a < 2; a++)
#pragma unroll
        for (int b = 0; b < 4; b++) wmma::fill_fragment(acc[a][b], 0.f);

#pragma unroll
    for (int kk = 0; kk < 6; kk++) {
        wmma::fragment<wmma::matrix_a, 16, 16, 16, bf16, wmma::row_major> a0, a1;
        wmma::fragment<wmma::matrix_b, 16, 16, 16, bf16, wmma::row_major> b[4];
        wmma::load_matrix_sync(a0, &sA[(wm * 32) * 104 + kk * 16], 104);
        wmma::load_matrix_sync(a1, &sA[(wm * 32 + 16) * 104 + kk * 16], 104);
#pragma unroll
        for (int j = 0; j < 4; j++)
            wmma::load_matrix_sync(b[j], &sB[(kk * 16) * 136 + wn * 64 + j * 16], 136);
#pragma unroll
        for (int j = 0; j < 4; j++) {
            wmma::mma_sync(acc[0][j], a0, b[j], acc[0][j]);
            wmma::mma_sync(acc[1][j], a1, b[j], acc[1][j]);
        }
    }
    __syncthreads();   // all mma reads of sA done before patch reuse

    float* patch = (float*)sA + warp * 16 * 20;
    int pr = lane >> 1, pc = (lane & 1) * 8;
#pragma unroll
    for (int im = 0; im < 2; im++) {
#pragma unroll
        for (int jn = 0; jn < 4; jn++) {
            wmma::store_matrix_sync(patch, acc[im][jn], 20, wmma::mem_row_major);
            __syncwarp();
            int kk_out = wm * 32 + im * 16 + pr;
            int n = nt * 128 + wn * 64 + jn * 16 + pc;
            int h = (n >> 6) & 7, kv = n >> 9, c = n & 63;
            bf16* drow = kvp + (((size_t)(i * 8 + h) * 2 + kv) * KP + kk_out) * DH + c;
            float4 v0 = *(float4*)&patch[pr * 20 + pc];
            float4 v1 = *(float4*)&patch[pr * 20 + pc + 4];
            __nv_bfloat162 h2[4] = {
                {__float2bfloat16(v0.x), __float2bfloat16(v0.y)},
                {__float2bfloat16(v0.z), __float2bfloat16(v0.w)},
                {__float2bfloat16(v1.x), __float2bfloat16(v1.y)},
                {__float2bfloat16(v1.z), __float2bfloat16(v1.w)}};
            *(float4*)drow = *(float4*)h2;
            __syncwarp();
        }
    }
}

// ---------------- Launch ----------------
template <typename T>
static T* sym_addr(const void* s) {
    void* p = nullptr;
    cudaGetSymbolAddress(&p, s);
    return (T*)p;
}

#define SMEM_T (2*64*72*2 + 64*328*4 + 64*296*2)   // 140288
#define SMEM_S (2*64*72*2 + 64*136*4 + 64*136*2)   // 70656

extern "C" void kernel_launch(void* const* d_in, const int* in_sizes, int n_in,
                              void* d_out, int out_size)
{
    (void)in_sizes; (void)n_in; (void)out_size;
    const float* x      = (const float*)d_in[0];
    const float* Wqkv_t = (const float*)d_in[1];
    const float* Wo_t   = (const float*)d_in[2];
    const float* Wqkv_s = (const float*)d_in[3];
    const float* Wo_s   = (const float*)d_in[4];
    const float* E      = (const float*)d_in[5];
    const float* W1     = (const float*)d_in[6];
    const float* b1     = (const float*)d_in[7];
    const float* W2     = (const float*)d_in[8];
    const float* b2     = (const float*)d_in[9];
    float* out = (float*)d_out;

    float* xt   = sym_addr<float>(g_xt);
    bf16*  xtb  = sym_addr<bf16>(b_xt);
    bf16*  qkv  = sym_addr<bf16>(b_qkv);
    bf16*  att  = sym_addr<bf16>(b_att);
    float* y1   = sym_addr<float>(g_y1);
    float* ys   = sym_addr<float>(g_ys);
    bf16*  ysb  = sym_addr<bf16>(b_ys);
    bf16*  kvp  = sym_addr<bf16>(b_kvp);
    bf16*  ffh  = sym_addr<bf16>(b_ffh);
    bf16*  outb = sym_addr<bf16>(b_out);
    bf16*  wqt  = sym_addr<bf16>(w_qkv_t);
    bf16*  wot  = sym_addr<bf16>(w_o_t);
    bf16*  wqs  = sym_addr<bf16>(w_qkv_s);
    bf16*  wos  = sym_addr<bf16>(w_o_s);
    bf16*  w1b  = sym_addr<bf16>(w_1);
    bf16*  w2b  = sym_addr<bf16>(w_2);
    bf16*  wET  = sym_addr<bf16>(w_ETp);

    static int smem_set = 0;
    if (!smem_set) {
        cudaFuncSetAttribute((const void*)fused_attn<5,257,288,328,296>,
                             cudaFuncAttributeMaxDynamicSharedMemorySize, SMEM_T);
        cudaFuncSetAttribute((const void*)fused_attn<2,128,128,136,136>,
                             cudaFuncAttributeMaxDynamicSharedMemorySize, SMEM_S);
        smem_set = 1;
    }

    // ---- weight conversion (single launch) + E^T ----
    ConvSegs cs;
    cs.src[0] = Wqkv_t; cs.dst[0] = wqt; cs.n4[0] = DIMD * LDQKV / 4;
    cs.src[1] = Wo_t;   cs.dst[1] = wot; cs.n4[1] = DIMD * DIMD / 4;
    cs.src[2] = Wqkv_s; cs.dst[2] = wqs; cs.n4[2] = DIMD * LDQKV / 4;
    cs.src[3] = Wo_s;   cs.dst[3] = wos; cs.n4[3] = DIMD * DIMD / 4;
    cs.src[4] = W1;     cs.dst[4] = w1b; cs.n4[4] = DIMD * DFF / 4;
    cs.src[5] = W2;     cs.dst[5] = w2b; cs.n4[5] = DFF * DIMD / 4;
    f2b_multi<<<dim3(DIMD * LDQKV / 4 / 256, 6), 256>>>(cs);
    build_ET<<<48, 256>>>(E, wET);

    // ---- temporal ----
    build_xt_kernel<<<NTOK1P, 128>>>(x, xt, xtb);

    gemm_bf128<<<dim3(LDQKV / 128, NTOK1P / 128), 256>>>(
        xtb, wqt, nullptr, qkv, nullptr, nullptr, LDQKV, DIMD, EPI_B16);

    fused_attn<5,257,288,328,296><<<dim3(5, B1 * HEADS), 256, SMEM_T>>>(
        qkv,        (long)T1 * LDQKV, LDQKV,
        qkv + 512,  (long)T1 * LDQKV, 64, LDQKV,
        qkv + 1024, (long)T1 * LDQKV, 64, LDQKV,
        att, (long)T1 * DIMD, T1, 0.125f);

    gemm_bf128<<<dim3(DIMD / 128, NTOK1P / 128), 256>>>(
        att, wot, y1, nullptr, nullptr, xt, DIMD, DIMD, EPI_R | EPI_F32);

    // ---- spatial ----
    build_ys_kernel<<<NTOK2, 128>>>(y1, ys, ysb);

    gemm_bf128<<<dim3(LDQKV / 128, NTOK2 / 128), 256>>>(
        ysb, wqs, nullptr, qkv, nullptr, nullptr, LDQKV, DIMD, EPI_B16);

    eproj_tc<<<dim3(8, B2), 256>>>(wET, qkv, kvp);

    fused_attn<2,128,128,136,136><<<dim3(2, B2 * HEADS), 256, SMEM_S>>>(
        qkv, (long)T2 * LDQKV, LDQKV,
        kvp,           16L * KP * DH, 2L * KP * DH, DH,
        kvp + KP * DH, 16L * KP * DH, 2L * KP * DH, DH,
        att, (long)T2 * DIMD, T2, 0.125f);

    gemm_bf128<<<dim3(DIMD / 128, NTOK2 / 128), 256>>>(
        att, wos, out, outb, nullptr, ys, DIMD, DIMD, EPI_R | EPI_F32 | EPI_B16);

    // ---- FFN ----
    gemm_bf128<<<dim3(DFF / 128, NTOK2 / 128), 256>>>(
        outb, w1b, nullptr, ffh, b1, nullptr, DFF, DIMD, EPI_BIAS | EPI_GELU | EPI_B16);

    gemm_bf128<<<dim3(DIMD / 128, NTOK2 / 128), 256>>>(
        ffh, w2b, out, nullptr, b2, out, DIMD, DFF, EPI_BIAS | EPI_R | EPI_F32);
}